// round 12
// baseline (speedup 1.0000x reference)
#include <cuda_runtime.h>
#include <math.h>
#include <stdint.h>

#define DDIM  128
#define MC    128          // rows per CTA
#define NB    128          // centers per B tile
#define NTILE 8            // K / NB
#define KCENT 1024
#define EPSF  1e-12f
#define THREADS 256

// ---------------- device scratch (no allocations allowed) -------------------
__device__ float    g_cf[KCENT * DDIM];   // normalized centers fp32 (prep tmp)
__device__ signed char g_cq[KCENT * DDIM]; // quantized centers s8, row-major
__device__ unsigned g_amax;               // global |c_hat| max (float bits)
__device__ double   g_sum;

// ---------------- helpers ---------------------------------------------------
__device__ __forceinline__ uint32_t smem_u32(const void* p) {
    uint32_t a;
    asm("{ .reg .u64 t; cvta.to.shared.u64 t, %1; cvt.u32.u64 %0, t; }"
        : "=r"(a) : "l"(p));
    return a;
}
__device__ __forceinline__ void cpa16(uint32_t dst, const void* src) {
    asm volatile("cp.async.cg.shared.global [%0], [%1], 16;"
                 :: "r"(dst), "l"(src));
}
__device__ __forceinline__ void cpa_commit() {
    asm volatile("cp.async.commit_group;" ::: "memory");
}
__device__ __forceinline__ void cpa_wait0() {
    asm volatile("cp.async.wait_group 0;" ::: "memory");
}
__device__ __forceinline__ void ldsm_x4(uint32_t* r, uint32_t addr) {
    asm volatile("ldmatrix.sync.aligned.m8n8.x4.shared.b16 {%0,%1,%2,%3}, [%4];"
                 : "=r"(r[0]), "=r"(r[1]), "=r"(r[2]), "=r"(r[3]) : "r"(addr));
}
// s8 MMA, k32, s32 accumulate
__device__ __forceinline__ void imma16832(int* d, const uint32_t* a,
                                          const uint32_t* b) {
    asm volatile(
        "mma.sync.aligned.m16n8k32.row.col.s32.s8.s8.s32 "
        "{%0,%1,%2,%3}, {%4,%5,%6,%7}, {%8,%9}, {%0,%1,%2,%3};"
        : "+r"(d[0]), "+r"(d[1]), "+r"(d[2]), "+r"(d[3])
        : "r"(a[0]), "r"(a[1]), "r"(a[2]), "r"(a[3]), "r"(b[0]), "r"(b[1]));
}
// s8 tile: 128-byte rows = 8 chunks of 16B, XOR-8 swizzle
__device__ __forceinline__ uint32_t swz8(uint32_t row, uint32_t ch) {
    return row * 128u + ((ch ^ (row & 7u)) << 4);
}

// ---------------------------------------------------------------------------
// Kernel Z: zero accumulators (must precede prep1's atomics).
// ---------------------------------------------------------------------------
__global__ void zero_kernel() {
    g_sum = 0.0;
    g_amax = 0u;
}

// ---------------------------------------------------------------------------
// Kernel A1: normalize centers -> fp32 scratch; global absmax via atomicMax.
// ---------------------------------------------------------------------------
__global__ void prep1_kernel(const float* __restrict__ centers) {
    int k = blockIdx.x;
    int t = threadIdx.x;

    float v = centers[(size_t)k * DDIM + t];
    float s = v * v;
    #pragma unroll
    for (int o = 16; o; o >>= 1) s += __shfl_xor_sync(0xffffffffu, s, o);

    __shared__ float ws[4];
    __shared__ float n2s;
    if ((t & 31) == 0) ws[t >> 5] = s;
    __syncthreads();
    if (t == 0) n2s = ws[0] + ws[1] + ws[2] + ws[3];
    __syncthreads();

    float ri = 1.0f / fmaxf(sqrtf(n2s), EPSF);
    float ch = v * ri;
    g_cf[(size_t)k * DDIM + t] = ch;

    float am = fabsf(ch);
    #pragma unroll
    for (int o = 16; o; o >>= 1) am = fmaxf(am, __shfl_xor_sync(0xffffffffu, am, o));
    __shared__ float wm[4];
    if ((t & 31) == 0) wm[t >> 5] = am;
    __syncthreads();
    if (t == 0) {
        float m = fmaxf(fmaxf(wm[0], wm[1]), fmaxf(wm[2], wm[3]));
        atomicMax(&g_amax, __float_as_uint(m));   // valid: values >= 0
    }
}

// ---------------------------------------------------------------------------
// Kernel A2: quantize centers to s8 with the global scale.
// ---------------------------------------------------------------------------
__global__ void prep2_kernel() {
    int i = blockIdx.x * blockDim.x + threadIdx.x;
    float qsc = 127.0f / __uint_as_float(g_amax);
    g_cq[i] = (signed char)__float2int_rn(g_cf[i] * qsc);
}

// ---------------------------------------------------------------------------
// Kernel B: s8 IMMA GEMM (sims, scale-free int argmax) + exact fp32 loss.
// 256 threads, 128 rows/CTA, 2 CTAs/SM. Warp tile 32(m) x 64(n); warps 4x2.
// ---------------------------------------------------------------------------
__global__ void __launch_bounds__(THREADS, 2) cluster_main_kernel(
    const float* __restrict__ features,
    const float* __restrict__ centers, int N)
{
    extern __shared__ char dsm[];
    // layout: A (16KB) | B[2] (32KB) | s_ri | s_bv[2][128] | s_bi[2][128] | spart
    const uint32_t Ab = smem_u32(dsm);
    const uint32_t Bb = Ab + 16384u;
    float* s_ri = (float*)(dsm + 49152);                 // 512 B
    int*   s_bv = (int*)  (dsm + 49152 + 512);           // 1024 B
    int*   s_bi = (int*)  (dsm + 49152 + 512 + 1024);    // 1024 B
    float* spart = (float*)(dsm + 49152 + 512 + 2048);   // 32 B

    const int tid  = threadIdx.x;
    const int lane = tid & 31;
    const int w    = tid >> 5;          // 0..7
    const int row0 = blockIdx.x * MC;

    // ---- kick off B tile 0 load (128 rows x 8 chunks = 1024 x 16B) ----
    {
        const char* src = (const char*)g_cq;
        #pragma unroll
        for (int j = tid; j < 1024; j += THREADS) {
            int n = j >> 3, c = j & 7;
            cpa16(Bb + swz8(n, c), src + n * 128 + c * 16);
        }
        cpa_commit();
    }

    // ---- phase 1: load 128 rows, normalize stats, quantize s8 -> smem A ----
    #pragma unroll 4
    for (int i = 0; i < 16; ++i) {
        int r = 16 * w + i;
        float4 v = *(const float4*)(features + (size_t)(row0 + r) * DDIM
                                    + 4 * lane);
        float s  = v.x * v.x + v.y * v.y + v.z * v.z + v.w * v.w;
        float am = fmaxf(fmaxf(fabsf(v.x), fabsf(v.y)),
                         fmaxf(fabsf(v.z), fabsf(v.w)));
        #pragma unroll
        for (int o = 16; o; o >>= 1) {
            s  += __shfl_xor_sync(0xffffffffu, s, o);
            am  = fmaxf(am, __shfl_xor_sync(0xffffffffu, am, o));
        }
        float ri = 1.0f / fmaxf(sqrtf(s), EPSF);
        if (lane == 0) s_ri[r] = ri;
        // q = round(f * 127/rowmax): per-row scale drops out of argmax
        float qs = 127.0f / am;
        int qx = __float2int_rn(v.x * qs);
        int qy = __float2int_rn(v.y * qs);
        int qz = __float2int_rn(v.z * qs);
        int qw = __float2int_rn(v.w * qs);
        uint32_t p = (uint32_t)(qx & 0xff) | ((uint32_t)(qy & 0xff) << 8)
                   | ((uint32_t)(qz & 0xff) << 16) | ((uint32_t)qw << 24);
        // lane's 4 dims = bytes 4*lane..+3 -> chunk lane>>2, offset (lane&3)*4
        uint32_t addr = Ab + swz8(r, lane >> 2) + (lane & 3) * 4;
        asm volatile("st.shared.b32 [%0], %1;" :: "r"(addr), "r"(p));
    }
    __syncthreads();

    // ---- warp tiling: 4(m) x 2(n), warp tile 32 x 64 ----
    const int wm = w & 3, wn = w >> 2;
    const int rb = 32 * wm;          // warp row base
    const int nb0 = 64 * wn;         // warp col base within tile

    int best_v[4];
    int best_i[4];
    #pragma unroll
    for (int s = 0; s < 4; ++s) { best_v[s] = -2147483647; best_i[s] = 0; }

    #pragma unroll 1
    for (int t = 0; t < NTILE; ++t) {
        cpa_wait0();
        __syncthreads();
        const uint32_t Bt = Bb + (uint32_t)(t & 1) * 16384u;

        if (t < NTILE - 1) {   // prefetch next tile into other buffer
            const char* src = (const char*)(g_cq + (size_t)(t + 1) * NB * DDIM);
            uint32_t dst = Bb + (uint32_t)((t + 1) & 1) * 16384u;
            #pragma unroll
            for (int j = tid; j < 1024; j += THREADS) {
                int n = j >> 3, c = j & 7;
                cpa16(dst + swz8(n, c), src + n * 128 + c * 16);
            }
            cpa_commit();
        }

        int acc[2][8][4];
        #pragma unroll
        for (int a = 0; a < 2; ++a)
            #pragma unroll
            for (int b = 0; b < 8; ++b)
                #pragma unroll
                for (int e = 0; e < 4; ++e) acc[a][b][e] = 0;

        #pragma unroll
        for (int ks = 0; ks < 4; ++ks) {    // k32 steps over D=128
            uint32_t a0[4], a1[4];
            {
                int row = rb + (lane & 15);
                int ch  = 2 * ks + (lane >> 4);     // 16B chunk = k-half
                ldsm_x4(a0, Ab + swz8(row, ch));
                ldsm_x4(a1, Ab + swz8(row + 16, ch));
            }
            uint32_t bfr[8][2];
            #pragma unroll
            for (int g = 0; g < 4; ++g) {
                int n  = nb0 + 16 * g + (lane & 7) + ((lane >> 4) << 3);
                int ch = 2 * ks + ((lane >> 3) & 1);
                uint32_t r4[4];
                ldsm_x4(r4, Bt + swz8(n, ch));
                bfr[2 * g][0] = r4[0]; bfr[2 * g][1] = r4[1];
                bfr[2 * g + 1][0] = r4[2]; bfr[2 * g + 1][1] = r4[3];
            }
            #pragma unroll
            for (int nt = 0; nt < 8; ++nt) {
                imma16832(acc[0][nt], a0, bfr[nt]);
                imma16832(acc[1][nt], a1, bfr[nt]);
            }
        }
        __syncthreads();   // all warps done reading Bt before it is refilled

        // fold int argmax: slot s = 2*mt + rh; rows rb + 16*mt + (lane>>2) + 8*rh
        const int kbase = t * NB + nb0 + 2 * (lane & 3);
        #pragma unroll
        for (int mt = 0; mt < 2; ++mt) {
            #pragma unroll
            for (int rh = 0; rh < 2; ++rh) {
                int s = 2 * mt + rh;
                #pragma unroll
                for (int nt = 0; nt < 8; ++nt) {
                    int v0 = acc[mt][nt][2 * rh];
                    int v1 = acc[mt][nt][2 * rh + 1];
                    int i0 = kbase + 8 * nt;
                    if (v0 > best_v[s]) { best_v[s] = v0; best_i[s] = i0; }
                    if (v1 > best_v[s]) { best_v[s] = v1; best_i[s] = i0 + 1; }
                }
            }
        }
    }

    // ---- reduce argmax over the 4 lanes of each quad ----
    #pragma unroll
    for (int off = 1; off < 4; off <<= 1) {
        #pragma unroll
        for (int s = 0; s < 4; ++s) {
            int ov = __shfl_down_sync(0xffffffffu, best_v[s], off);
            int oi = __shfl_down_sync(0xffffffffu, best_i[s], off);
            if (ov > best_v[s] || (ov == best_v[s] && oi < best_i[s])) {
                best_v[s] = ov; best_i[s] = oi;
            }
        }
    }
    // each n-warp half writes its OWN slot (no cross-half race)
    if ((lane & 3) == 0) {
        int q = lane >> 2;
        #pragma unroll
        for (int s = 0; s < 4; ++s) {
            int mt = s >> 1, rh = s & 1;
            int r = rb + 16 * mt + 8 * rh + q;
            s_bv[wn * MC + r] = best_v[s];
            s_bi[wn * MC + r] = best_i[s];
        }
    }
    __syncthreads();

    // ---- phase 3: merge halves + exact fp32 loss (2 threads/row) ----
    {
        int r = tid >> 1;        // 0..127
        int hq = tid & 1;        // dim half
        int v0 = s_bv[r],  v1 = s_bv[MC + r];
        int i0 = s_bi[r],  i1 = s_bi[MC + r];
        int bi = (v1 > v0 || (v1 == v0 && i1 < i0)) ? i1 : i0;
        float ri = s_ri[r];
        const float4* fp = (const float4*)(features + (size_t)(row0 + r) * DDIM)
                         + 16 * hq;
        const float4* cp = (const float4*)(centers + (size_t)bi * DDIM) + 16 * hq;
        float ls = 0.0f;
        #pragma unroll
        for (int j = 0; j < 16; ++j) {
            float4 f = fp[j], c = cp[j];
            float dx = fmaf(f.x, ri, -c.x);
            float dy = fmaf(f.y, ri, -c.y);
            float dz = fmaf(f.z, ri, -c.z);
            float dw = fmaf(f.w, ri, -c.w);
            ls += dx * dx + dy * dy + dz * dz + dw * dw;
        }
        #pragma unroll
        for (int o = 16; o; o >>= 1) ls += __shfl_xor_sync(0xffffffffu, ls, o);
        if (lane == 0) spart[w] = ls;
    }
    __syncthreads();
    if (tid == 0) {
        float bs = 0.0f;
        #pragma unroll
        for (int i = 0; i < 8; ++i) bs += spart[i];
        atomicAdd(&g_sum, (double)bs);
    }
}

// ---------------------------------------------------------------------------
__global__ void finalize_kernel(float* out, int N) {
    out[0] = (float)(g_sum / (double)N);
}

extern "C" void kernel_launch(void* const* d_in, const int* in_sizes, int n_in,
                              void* d_out, int out_size) {
    const float* features = (const float*)d_in[0];
    const float* centers  = (const float*)d_in[1];
    int N = in_sizes[0] / DDIM;

    const int smem_bytes = 49152 + 512 + 2048 + 32;
    cudaFuncSetAttribute(cluster_main_kernel,
                         cudaFuncAttributeMaxDynamicSharedMemorySize, smem_bytes);

    zero_kernel<<<1, 1>>>();
    prep1_kernel<<<KCENT, 128>>>(centers);
    prep2_kernel<<<KCENT, 128>>>();
    cluster_main_kernel<<<N / MC, THREADS, smem_bytes>>>(features, centers, N);
    finalize_kernel<<<1, 1>>>((float*)d_out, N);
}

// round 13
// speedup vs baseline: 1.3227x; 1.3227x over previous
#include <cuda_runtime.h>
#include <cuda_bf16.h>
#include <math.h>
#include <stdint.h>

#define DDIM  128
#define MC    128          // rows per CTA
#define NB    128          // centers per B tile
#define KHT   4            // B tiles per CTA (split-K half: 512 centers)
#define KCENT 1024
#define NROWS 131072
#define EPSF  1e-12f
#define THREADS 256

// ---------------- device scratch (no allocations allowed) -------------------
__device__ __nv_bfloat16 g_cbf[KCENT * DDIM];   // normalized centers, bf16
__device__ float  g_sbv[2 * NROWS];             // per-khalf best sim
__device__ int    g_sbi[2 * NROWS];             // per-khalf best index
__device__ int    g_tix[NROWS / MC];            // per-rowblock tickets
__device__ double g_sum;

// ---------------- helpers ---------------------------------------------------
__device__ __forceinline__ uint32_t smem_u32(const void* p) {
    uint32_t a;
    asm("{ .reg .u64 t; cvta.to.shared.u64 t, %1; cvt.u32.u64 %0, t; }"
        : "=r"(a) : "l"(p));
    return a;
}
__device__ __forceinline__ void cpa16(uint32_t dst, const void* src) {
    asm volatile("cp.async.cg.shared.global [%0], [%1], 16;"
                 :: "r"(dst), "l"(src));
}
__device__ __forceinline__ void cpa_commit() {
    asm volatile("cp.async.commit_group;" ::: "memory");
}
__device__ __forceinline__ void cpa_wait0() {
    asm volatile("cp.async.wait_group 0;" ::: "memory");
}
__device__ __forceinline__ void ldsm_x4(uint32_t* r, uint32_t addr) {
    asm volatile("ldmatrix.sync.aligned.m8n8.x4.shared.b16 {%0,%1,%2,%3}, [%4];"
                 : "=r"(r[0]), "=r"(r[1]), "=r"(r[2]), "=r"(r[3]) : "r"(addr));
}
__device__ __forceinline__ void mma16816(float* d, const uint32_t* a,
                                         const uint32_t* b) {
    asm volatile(
        "mma.sync.aligned.m16n8k16.row.col.f32.bf16.bf16.f32 "
        "{%0,%1,%2,%3}, {%4,%5,%6,%7}, {%8,%9}, {%0,%1,%2,%3};"
        : "+f"(d[0]), "+f"(d[1]), "+f"(d[2]), "+f"(d[3])
        : "r"(a[0]), "r"(a[1]), "r"(a[2]), "r"(a[3]), "r"(b[0]), "r"(b[1]));
}
__device__ __forceinline__ uint32_t pack_bf2(float a, float b) {
    __nv_bfloat16 ha = __float2bfloat16(a);
    __nv_bfloat16 hb = __float2bfloat16(b);
    return (uint32_t)__bfloat16_as_ushort(ha)
         | ((uint32_t)__bfloat16_as_ushort(hb) << 16);
}
// row-major bf16 tile, 256B rows (16 x 16B chunks), XOR-8 swizzle
__device__ __forceinline__ uint32_t swz(uint32_t row, uint32_t chunk) {
    return row * 256u + ((chunk ^ (row & 7u)) << 4);
}

// ---------------------------------------------------------------------------
// Kernel Z: zero accumulator + tickets.
// ---------------------------------------------------------------------------
__global__ void zero_kernel() {
    int i = threadIdx.x;
    g_tix[i] = 0;
    if (i == 0) g_sum = 0.0;
}

// ---------------------------------------------------------------------------
// Kernel A: normalize centers -> bf16 row-major.
// ---------------------------------------------------------------------------
__global__ void prep_centers_kernel(const float* __restrict__ centers) {
    int k = blockIdx.x;
    int t = threadIdx.x;

    float v = centers[(size_t)k * DDIM + t];
    float s = v * v;
    #pragma unroll
    for (int o = 16; o; o >>= 1) s += __shfl_xor_sync(0xffffffffu, s, o);

    __shared__ float ws[4];
    __shared__ float n2s;
    if ((t & 31) == 0) ws[t >> 5] = s;
    __syncthreads();
    if (t == 0) n2s = ws[0] + ws[1] + ws[2] + ws[3];
    __syncthreads();

    float ri = 1.0f / fmaxf(sqrtf(n2s), EPSF);
    g_cbf[(size_t)k * DDIM + t] = __float2bfloat16(v * ri);
}

// ---------------------------------------------------------------------------
// Kernel B: bf16 mma.sync GEMM + argmax over a 512-center K-half.
// grid = 2 * (N/MC). bid&1 = khalf. Second CTA finishing a rowblock does
// the cross-half merge + exact fp32 loss (threadfence-ticket pattern).
// 256 threads, 2 CTAs/SM. Warp tile 32(m) x 64(n); warps 4(m) x 2(n).
// ---------------------------------------------------------------------------
__global__ void __launch_bounds__(THREADS, 2) cluster_main_kernel(
    const float* __restrict__ features,
    const float* __restrict__ centers, int N)
{
    extern __shared__ char dsm[];
    // layout: A (32KB) | B[2] (64KB) | s_ri | s_bv[2][128] | s_bi[2][128] | spart
    const uint32_t Ab = smem_u32(dsm);
    const uint32_t Bb = Ab + 32768u;
    float* s_ri = (float*)(dsm + 98304);                 // 512 B
    float* s_bv = (float*)(dsm + 98304 + 512);           // 1024 B
    int*   s_bi = (int*)  (dsm + 98304 + 512 + 1024);    // 1024 B
    float* spart = (float*)(dsm + 98304 + 512 + 2048);   // 32 B

    __shared__ int s_old;

    const int tid  = threadIdx.x;
    const int lane = tid & 31;
    const int w    = tid >> 5;          // 0..7
    const int rowblk = blockIdx.x >> 1;
    const int khalf  = blockIdx.x & 1;
    const int row0   = rowblk * MC;
    const int t0     = khalf * KHT;     // first B tile index

    // ---- kick off first B tile load ----
    {
        const char* src = (const char*)(g_cbf + (size_t)t0 * NB * DDIM);
        #pragma unroll
        for (int j = tid; j < 2048; j += THREADS) {
            int n = j >> 4, c = j & 15;
            cpa16(Bb + swz(n, c), src + n * 256 + c * 16);
        }
        cpa_commit();
    }

    // ---- phase 1: load 128 feature rows, normalize, bf16 -> smem A ----
    #pragma unroll 4
    for (int i = 0; i < 16; ++i) {
        int r = 16 * w + i;
        float4 v = *(const float4*)(features + (size_t)(row0 + r) * DDIM
                                    + 4 * lane);
        float s = v.x * v.x + v.y * v.y + v.z * v.z + v.w * v.w;
        #pragma unroll
        for (int o = 16; o; o >>= 1) s += __shfl_xor_sync(0xffffffffu, s, o);
        float ri = 1.0f / fmaxf(sqrtf(s), EPSF);
        if (lane == 0) s_ri[r] = ri;
        uint32_t p0 = pack_bf2(v.x * ri, v.y * ri);
        uint32_t p1 = pack_bf2(v.z * ri, v.w * ri);
        uint32_t addr = Ab + swz(r, lane >> 1) + (lane & 1) * 8;
        asm volatile("st.shared.v2.b32 [%0], {%1,%2};"
                     :: "r"(addr), "r"(p0), "r"(p1));
    }
    __syncthreads();

    // ---- warp tiling: 4(m) x 2(n), warp tile 32 x 64 ----
    const int wm = w & 3, wn = w >> 2;
    const int rb = 32 * wm;
    const int nb0 = 64 * wn;

    float best_v[4];
    int   best_i[4];
    #pragma unroll
    for (int s = 0; s < 4; ++s) { best_v[s] = -INFINITY; best_i[s] = 0; }

    #pragma unroll 1
    for (int tt = 0; tt < KHT; ++tt) {
        const int t = t0 + tt;
        cpa_wait0();
        __syncthreads();
        const uint32_t Bt = Bb + (uint32_t)(tt & 1) * 32768u;

        if (tt < KHT - 1) {   // prefetch next tile into other buffer
            const char* src = (const char*)(g_cbf + (size_t)(t + 1) * NB * DDIM);
            uint32_t dst = Bb + (uint32_t)((tt + 1) & 1) * 32768u;
            #pragma unroll
            for (int j = tid; j < 2048; j += THREADS) {
                int n = j >> 4, c = j & 15;
                cpa16(dst + swz(n, c), src + n * 256 + c * 16);
            }
            cpa_commit();
        }

        float acc[2][8][4];
        #pragma unroll
        for (int a = 0; a < 2; ++a)
            #pragma unroll
            for (int b = 0; b < 8; ++b)
                #pragma unroll
                for (int e = 0; e < 4; ++e) acc[a][b][e] = 0.0f;

        #pragma unroll
        for (int ks = 0; ks < 8; ++ks) {
            uint32_t a0[4], a1[4];
            {
                int row = rb + (lane & 15);
                int ch  = 2 * ks + (lane >> 4);
                ldsm_x4(a0, Ab + swz(row, ch));
                ldsm_x4(a1, Ab + swz(row + 16, ch));
            }
            uint32_t bfr[8][2];
            #pragma unroll
            for (int g = 0; g < 4; ++g) {
                int n  = nb0 + 16 * g + (lane & 7) + ((lane >> 4) << 3);
                int ch = 2 * ks + ((lane >> 3) & 1);
                uint32_t r4[4];
                ldsm_x4(r4, Bt + swz(n, ch));
                bfr[2 * g][0] = r4[0]; bfr[2 * g][1] = r4[1];
                bfr[2 * g + 1][0] = r4[2]; bfr[2 * g + 1][1] = r4[3];
            }
            #pragma unroll
            for (int nt = 0; nt < 8; ++nt) {
                mma16816(acc[0][nt], a0, bfr[nt]);
                mma16816(acc[1][nt], a1, bfr[nt]);
            }
        }
        __syncthreads();   // all warps done reading Bt before refill

        const int kbase = t * NB + nb0 + 2 * (lane & 3);
        #pragma unroll
        for (int mt = 0; mt < 2; ++mt) {
            #pragma unroll
            for (int rh = 0; rh < 2; ++rh) {
                int s = 2 * mt + rh;
                #pragma unroll
                for (int nt = 0; nt < 8; ++nt) {
                    float v0 = acc[mt][nt][2 * rh];
                    float v1 = acc[mt][nt][2 * rh + 1];
                    int   i0 = kbase + 8 * nt;
                    if (v0 > best_v[s]) { best_v[s] = v0; best_i[s] = i0; }
                    if (v1 > best_v[s]) { best_v[s] = v1; best_i[s] = i0 + 1; }
                }
            }
        }
    }

    // ---- reduce argmax over the 4 lanes of each quad ----
    #pragma unroll
    for (int off = 1; off < 4; off <<= 1) {
        #pragma unroll
        for (int s = 0; s < 4; ++s) {
            float ov = __shfl_down_sync(0xffffffffu, best_v[s], off);
            int   oi = __shfl_down_sync(0xffffffffu, best_i[s], off);
            if (ov > best_v[s] || (ov == best_v[s] && oi < best_i[s])) {
                best_v[s] = ov; best_i[s] = oi;
            }
        }
    }
    if ((lane & 3) == 0) {
        int q = lane >> 2;
        #pragma unroll
        for (int s = 0; s < 4; ++s) {
            int mt = s >> 1, rh = s & 1;
            int r = rb + 16 * mt + 8 * rh + q;
            s_bv[wn * MC + r] = best_v[s];
            s_bi[wn * MC + r] = best_i[s];
        }
    }
    __syncthreads();

    // ---- merge n-halves, publish this khalf's per-row candidate ----
    if (tid < MC) {
        int r = tid;
        float v0 = s_bv[r], v1 = s_bv[MC + r];
        int   i0 = s_bi[r], i1 = s_bi[MC + r];
        bool take1 = (v1 > v0) || (v1 == v0 && i1 < i0);
        g_sbv[(size_t)khalf * NROWS + row0 + r] = take1 ? v1 : v0;
        g_sbi[(size_t)khalf * NROWS + row0 + r] = take1 ? i1 : i0;
    }
    __threadfence();
    __syncthreads();
    if (tid == 0) s_old = atomicAdd(&g_tix[rowblk], 1);
    __syncthreads();
    if (s_old == 0) return;          // first finisher: done
    __threadfence();                 // order: see peer's scratch writes

    // ---- phase 3 (second finisher): merge khalves + exact fp32 loss ----
    {
        int r = tid >> 1;        // 0..127
        int hq = tid & 1;        // dim half
        float v0 = g_sbv[row0 + r],        v1 = g_sbv[NROWS + row0 + r];
        int   i0 = g_sbi[row0 + r],        i1 = g_sbi[NROWS + row0 + r];
        int bi = (v1 > v0 || (v1 == v0 && i1 < i0)) ? i1 : i0;
        float ri = s_ri[r];
        const float4* fp = (const float4*)(features + (size_t)(row0 + r) * DDIM)
                         + 16 * hq;
        const float4* cp = (const float4*)(centers + (size_t)bi * DDIM) + 16 * hq;
        float ls = 0.0f;
        #pragma unroll
        for (int j = 0; j < 16; ++j) {
            float4 f = fp[j], c = cp[j];
            float dx = fmaf(f.x, ri, -c.x);
            float dy = fmaf(f.y, ri, -c.y);
            float dz = fmaf(f.z, ri, -c.z);
            float dw = fmaf(f.w, ri, -c.w);
            ls += dx * dx + dy * dy + dz * dz + dw * dw;
        }
        #pragma unroll
        for (int o = 16; o; o >>= 1) ls += __shfl_xor_sync(0xffffffffu, ls, o);
        if (lane == 0) spart[w] = ls;
    }
    __syncthreads();
    if (tid == 0) {
        float bs = 0.0f;
        #pragma unroll
        for (int i = 0; i < 8; ++i) bs += spart[i];
        atomicAdd(&g_sum, (double)bs);
    }
}

// ---------------------------------------------------------------------------
__global__ void finalize_kernel(float* out, int N) {
    out[0] = (float)(g_sum / (double)N);
}

extern "C" void kernel_launch(void* const* d_in, const int* in_sizes, int n_in,
                              void* d_out, int out_size) {
    const float* features = (const float*)d_in[0];
    const float* centers  = (const float*)d_in[1];
    int N = in_sizes[0] / DDIM;

    const int smem_bytes = 98304 + 512 + 2048 + 32;
    cudaFuncSetAttribute(cluster_main_kernel,
                         cudaFuncAttributeMaxDynamicSharedMemorySize, smem_bytes);

    zero_kernel<<<1, NROWS / MC>>>();
    prep_centers_kernel<<<KCENT, 128>>>(centers);
    cluster_main_kernel<<<2 * (N / MC), THREADS, smem_bytes>>>(features, centers, N);
    finalize_kernel<<<1, 1>>>((float*)d_out, N);
}